// round 5
// baseline (speedup 1.0000x reference)
#include <cuda_runtime.h>
#include <math.h>

#define N_NODES 20000
#define S_TOK   8
#define D_DIM   128
#define E_EDGES 100000
#define NS      (N_NODES * S_TOK)   // 160000 rows

// ---------------- static scratch (no allocs allowed) ----------------
__device__ float g_projD[(size_t)NS * 384];   // per-dst-node Q|Kd|Vd   (245.8 MB)
__device__ float g_projS[(size_t)NS * 256];   // per-src-node Ks|Vs     (163.8 MB)
__device__ float g_sumO [(size_t)NS * 128];   // attention-output accum (81.9 MB)
__device__ int   g_cnt  [N_NODES];
__device__ float g_WT   [128 * 384];          // Win transposed [K, 3D]
__device__ float g_WTs  [128 * 256];          // combined (Wk*Wb | Wv*Wb) transposed
__device__ float g_bS   [256];                // combined src biases
__device__ float g_WoT  [128 * 128];          // Wo transposed

// ---------------- counts ----------------
__global__ void count_kernel(const int* __restrict__ dst, int* __restrict__ cnt) {
    int e = blockIdx.x * blockDim.x + threadIdx.x;
    if (e < E_EDGES) atomicAdd(&cnt[dst[e]], 1);
}

// ---------------- weight prep ----------------
// WT[k*rows + o] = W[o*128 + k]
__global__ void transpose_w_kernel(const float* __restrict__ W, float* __restrict__ WT, int rows) {
    int idx = blockIdx.x * blockDim.x + threadIdx.x;
    if (idx < rows * 128) {
        int k = idx / rows, o = idx % rows;
        WT[idx] = W[o * 128 + k];
    }
}

// Combined source-side weights: Ks = x_src @ (Wk Wb)^T + (Wk bb + bk); same for V.
// Writes transposed: WTs[k*256 + o] (o<128 -> K, else V), biases into bS[256].
__global__ void combine_src_kernel(const float* __restrict__ Win, const float* __restrict__ binp,
                                   const float* __restrict__ Wb,  const float* __restrict__ bb,
                                   float* __restrict__ WTs, float* __restrict__ bS) {
    int o = blockIdx.x;   // 0..127
    int k = threadIdx.x;  // 0..127
    const float* wkrow = Win + (128 + o) * 128;
    const float* wvrow = Win + (256 + o) * 128;
    float sk = 0.f, sv = 0.f;
    for (int j = 0; j < 128; j++) {
        float wb = Wb[j * 128 + k];
        sk += wkrow[j] * wb;
        sv += wvrow[j] * wb;
    }
    WTs[k * 256 + o]       = sk;
    WTs[k * 256 + 128 + o] = sv;
    if (k == 0) {
        float s = 0.f;
        for (int j = 0; j < 128; j++) s += wkrow[j] * bb[j];
        bS[o] = s + binp[128 + o];
    } else if (k == 1) {
        float s = 0.f;
        for (int j = 0; j < 128; j++) s += wvrow[j] * bb[j];
        bS[128 + o] = s + binp[256 + o];
    }
}

// ---------------- SGEMM: C[M,Nn] = alpha*(A[M,128] @ B[128,Nn] + bias*ind) (+C) ----------------
// flags: bit0 accumulate into C; bit1 scale A rows by 1/max(cnt[row/8],1); bit2 bias gated by cnt>0
__global__ __launch_bounds__(256) void sgemm_k128(
    const float* __restrict__ A, const float* __restrict__ B,
    const float* __restrict__ bias, const int* __restrict__ cnt,
    float* __restrict__ C, int Nn, float alpha, int flags)
{
    __shared__ float As[16][64];
    __shared__ float Bs[16][64];
    const int tid = threadIdx.x;
    const int bm = blockIdx.x * 64;
    const int bn = blockIdx.y * 64;
    const int tx = tid & 15;        // N direction (4 cols each)
    const int ty = tid >> 4;        // M direction (4 rows each)
    const int lrow = tid >> 2;      // A-load row within tile
    const int lseg = tid & 3;       // A-load float4 segment

    float rs = 1.0f;
    if (flags & 2) {
        int c = cnt[(bm + lrow) >> 3];
        rs = 1.0f / (float)(c > 1 ? c : 1);
    }
    const float* Ap = A + (size_t)(bm + lrow) * 128 + lseg * 4;
    const float* Bp = B + (size_t)ty * Nn + bn + tx * 4;

    float acc[4][4];
    #pragma unroll
    for (int i = 0; i < 4; i++)
        #pragma unroll
        for (int j = 0; j < 4; j++) acc[i][j] = 0.f;

    #pragma unroll
    for (int k0 = 0; k0 < 128; k0 += 16) {
        float4 av = *(const float4*)(Ap + k0);
        As[lseg * 4 + 0][lrow] = av.x * rs;
        As[lseg * 4 + 1][lrow] = av.y * rs;
        As[lseg * 4 + 2][lrow] = av.z * rs;
        As[lseg * 4 + 3][lrow] = av.w * rs;
        *(float4*)&Bs[ty][tx * 4] = *(const float4*)(Bp + (size_t)k0 * Nn);
        __syncthreads();
        #pragma unroll
        for (int k = 0; k < 16; k++) {
            float4 a4 = *(const float4*)&As[k][ty * 4];
            float4 b4 = *(const float4*)&Bs[k][tx * 4];
            float aa[4]  = {a4.x, a4.y, a4.z, a4.w};
            float bbv[4] = {b4.x, b4.y, b4.z, b4.w};
            #pragma unroll
            for (int i = 0; i < 4; i++)
                #pragma unroll
                for (int j = 0; j < 4; j++)
                    acc[i][j] += aa[i] * bbv[j];
        }
        __syncthreads();
    }

    float bvv[4] = {0.f, 0.f, 0.f, 0.f};
    if (bias) {
        #pragma unroll
        for (int j = 0; j < 4; j++) bvv[j] = bias[bn + tx * 4 + j];
    }
    #pragma unroll
    for (int i = 0; i < 4; i++) {
        int row = bm + ty * 4 + i;
        float ind = 1.0f;
        if (flags & 4) ind = (cnt[row >> 3] > 0) ? 1.0f : 0.0f;
        float* cp = C + (size_t)row * Nn + bn + tx * 4;
        #pragma unroll
        for (int j = 0; j < 4; j++) {
            float v = alpha * (acc[i][j] + bvv[j] * ind);
            if (flags & 1) cp[j] += v; else cp[j] = v;
        }
    }
}

// ---------------- per-edge attention + scatter-sum ----------------
// One block per edge, 128 threads = 4 warps = 4 heads.
// Keys/values: rows 0..7 = dst self part (Kd/Vd), rows 8..15 = source part (Ks/Vs).
__global__ __launch_bounds__(128) void edge_attn_kernel(
    const int* __restrict__ ei,
    const float* __restrict__ projD, const float* __restrict__ projS,
    float* __restrict__ sumO)
{
    __shared__ float sQ[8][132];
    __shared__ float sK[16][132];
    __shared__ float sV[16][132];
    const int e   = blockIdx.x;
    const int src = ei[e];
    const int dst = ei[E_EDGES + e];
    const int tid = threadIdx.x;

    {
        const float* base = projD + (size_t)dst * 8 * 384;
        const float* sbase = projS + (size_t)src * 8 * 256;
        #pragma unroll
        for (int idx = tid; idx < 256; idx += 128) {
            int r = idx >> 5, c = (idx & 31) << 2;
            *(float4*)&sQ[r][c]     = *(const float4*)(base + r * 384 + c);
            *(float4*)&sK[r][c]     = *(const float4*)(base + r * 384 + 128 + c);
            *(float4*)&sV[r][c]     = *(const float4*)(base + r * 384 + 256 + c);
            *(float4*)&sK[8 + r][c] = *(const float4*)(sbase + r * 256 + c);
            *(float4*)&sV[8 + r][c] = *(const float4*)(sbase + r * 256 + 128 + c);
        }
    }
    __syncthreads();

    const int h    = tid >> 5;
    const int lane = tid & 31;
    const int i    = lane >> 2;        // query row 0..7
    const int j0   = (lane & 3) << 2;  // this lane's 4 keys
    const int c0   = h * 32;

    float q[32];
    #pragma unroll
    for (int d = 0; d < 32; d++) q[d] = sQ[i][c0 + d];

    const float scale = 0.17677669529663687f;  // 1/sqrt(32)
    float s[4];
    #pragma unroll
    for (int t = 0; t < 4; t++) {
        const float* kk = &sK[j0 + t][c0];
        float a = 0.f;
        #pragma unroll
        for (int d = 0; d < 32; d++) a += q[d] * kk[d];
        s[t] = a * scale;
    }

    // softmax over 16 keys spread across 4 consecutive lanes
    float m = fmaxf(fmaxf(s[0], s[1]), fmaxf(s[2], s[3]));
    m = fmaxf(m, __shfl_xor_sync(0xffffffffu, m, 1));
    m = fmaxf(m, __shfl_xor_sync(0xffffffffu, m, 2));
    float ev[4]; float Z = 0.f;
    #pragma unroll
    for (int t = 0; t < 4; t++) { ev[t] = __expf(s[t] - m); Z += ev[t]; }
    Z += __shfl_xor_sync(0xffffffffu, Z, 1);
    Z += __shfl_xor_sync(0xffffffffu, Z, 2);

    float o[32];
    #pragma unroll
    for (int d = 0; d < 32; d++) o[d] = 0.f;
    #pragma unroll
    for (int t = 0; t < 4; t++) {
        const float* vv = &sV[j0 + t][c0];
        #pragma unroll
        for (int d = 0; d < 32; d++) o[d] += ev[t] * vv[d];
    }
    #pragma unroll
    for (int d = 0; d < 32; d++) {
        o[d] += __shfl_xor_sync(0xffffffffu, o[d], 1);
        o[d] += __shfl_xor_sync(0xffffffffu, o[d], 2);
    }
    float invZ = 1.0f / Z;

    float* op = sumO + ((size_t)dst * 8 + i) * 128 + c0;
    const int dq = (lane & 3) * 8;     // each lane writes its 8-wide quarter
    #pragma unroll
    for (int d = 0; d < 32; d++) {
        if ((d & ~7) == dq) atomicAdd(&op[d], o[d] * invZ);
    }
}

// ---------------- launch ----------------
extern "C" void kernel_launch(void* const* d_in, const int* in_sizes, int n_in,
                              void* d_out, int out_size)
{
    const float* x_a = (const float*)d_in[0];
    const float* x_b = (const float*)d_in[1];
    const int* ei[3] = {(const int*)d_in[2], (const int*)d_in[3], (const int*)d_in[4]};
    const float *Wb[3], *bb[3], *Win[3], *bin[3], *Wo[3], *bo[3];
    for (int r = 0; r < 3; r++) {
        Wb[r]  = (const float*)d_in[5 + 6 * r];
        bb[r]  = (const float*)d_in[6 + 6 * r];
        Win[r] = (const float*)d_in[7 + 6 * r];
        bin[r] = (const float*)d_in[8 + 6 * r];
        Wo[r]  = (const float*)d_in[9 + 6 * r];
        bo[r]  = (const float*)d_in[10 + 6 * r];
    }

    float *projD, *projS, *sumO, *WT, *WTs, *bS, *WoT; int* cnt;
    cudaGetSymbolAddress((void**)&projD, g_projD);
    cudaGetSymbolAddress((void**)&projS, g_projS);
    cudaGetSymbolAddress((void**)&sumO,  g_sumO);
    cudaGetSymbolAddress((void**)&cnt,   g_cnt);
    cudaGetSymbolAddress((void**)&WT,    g_WT);
    cudaGetSymbolAddress((void**)&WTs,   g_WTs);
    cudaGetSymbolAddress((void**)&bS,    g_bS);
    cudaGetSymbolAddress((void**)&WoT,   g_WoT);

    float* outA = (float*)d_out;                       // stack index 0
    float* outB = (float*)d_out + (size_t)NS * 128;    // stack index 1

    const float* xs[3]  = {x_a, x_b, x_a};   // source table per relation
    const float* xd[3]  = {x_b, x_a, x_a};   // dest table per relation
    float*       op[3]  = {outB, outA, outA};
    const float  al[3]  = {1.0f, 0.5f, 0.5f};
    const int    ac[3]  = {0, 0, 1};

    for (int r = 0; r < 3; r++) {
        cudaMemsetAsync(cnt, 0, N_NODES * sizeof(int), 0);
        count_kernel<<<(E_EDGES + 255) / 256, 256>>>(ei[r] + E_EDGES, cnt);

        transpose_w_kernel<<<(384 * 128 + 255) / 256, 256>>>(Win[r], WT, 384);
        combine_src_kernel<<<128, 128>>>(Win[r], bin[r], Wb[r], bb[r], WTs, bS);
        transpose_w_kernel<<<(128 * 128 + 255) / 256, 256>>>(Wo[r], WoT, 128);

        // Per-node projections
        {
            dim3 g(NS / 64, 384 / 64);
            sgemm_k128<<<g, 256>>>(xd[r], WT, bin[r], nullptr, projD, 384, 1.0f, 0);
        }
        {
            dim3 g(NS / 64, 256 / 64);
            sgemm_k128<<<g, 256>>>(xs[r], WTs, bS, nullptr, projS, 256, 1.0f, 0);
        }

        cudaMemsetAsync(sumO, 0, (size_t)NS * 128 * sizeof(float), 0);
        edge_attn_kernel<<<E_EDGES, 128>>>(ei[r], projD, projS, sumO);

        // mean + Wo projection + (gated) bias, scaled/accumulated into output
        {
            dim3 g(NS / 64, 128 / 64);
            sgemm_k128<<<g, 256>>>(sumO, WoT, bo[r], cnt, op[r], 128, al[r],
                                   ac[r] | 2 | 4);
        }
    }
}

// round 8
// speedup vs baseline: 1.5069x; 1.5069x over previous
#include <cuda_runtime.h>
#include <math.h>

#define N_NODES 20000
#define S_TOK   8
#define D_DIM   128
#define E_EDGES 100000
#define NS      (N_NODES * S_TOK)   // 160000 rows

// ---------------- static scratch (no allocs allowed) ----------------
__device__ float g_projD[(size_t)NS * 384];   // per-dst-node Q|Kd|Vd
__device__ float g_projS[(size_t)NS * 256];   // per-src-node Ks|Vs
__device__ float g_sumO [(size_t)NS * 128];   // attention-output accum
__device__ float g_selfS[(size_t)N_NODES * 256]; // per-node self scores [h][i][j]
__device__ int   g_cnt  [N_NODES];
__device__ float g_WT   [128 * 384];          // Win transposed [K, 3D]
__device__ float g_WTs  [128 * 256];          // combined (Wk*Wb | Wv*Wb) transposed
__device__ float g_bS   [256];                // combined src biases
__device__ float g_WoT  [128 * 128];          // Wo transposed

// ---------------- counts ----------------
__global__ void count_kernel(const int* __restrict__ dst, int* __restrict__ cnt) {
    int e = blockIdx.x * blockDim.x + threadIdx.x;
    if (e < E_EDGES) atomicAdd(&cnt[dst[e]], 1);
}

// ---------------- weight prep ----------------
__global__ void transpose_w_kernel(const float* __restrict__ W, float* __restrict__ WT, int rows) {
    int idx = blockIdx.x * blockDim.x + threadIdx.x;
    if (idx < rows * 128) {
        int k = idx / rows, o = idx % rows;
        WT[idx] = W[o * 128 + k];
    }
}

__global__ void combine_src_kernel(const float* __restrict__ Win, const float* __restrict__ binp,
                                   const float* __restrict__ Wb,  const float* __restrict__ bb,
                                   float* __restrict__ WTs, float* __restrict__ bS) {
    int o = blockIdx.x;   // 0..127
    int k = threadIdx.x;  // 0..127
    const float* wkrow = Win + (128 + o) * 128;
    const float* wvrow = Win + (256 + o) * 128;
    float sk = 0.f, sv = 0.f;
    for (int j = 0; j < 128; j++) {
        float wb = Wb[j * 128 + k];
        sk += wkrow[j] * wb;
        sv += wvrow[j] * wb;
    }
    WTs[k * 256 + o]       = sk;
    WTs[k * 256 + 128 + o] = sv;
    if (k == 0) {
        float s = 0.f;
        for (int j = 0; j < 128; j++) s += wkrow[j] * bb[j];
        bS[o] = s + binp[128 + o];
    } else if (k == 1) {
        float s = 0.f;
        for (int j = 0; j < 128; j++) s += wvrow[j] * bb[j];
        bS[128 + o] = s + binp[256 + o];
    }
}

// ---------------- SGEMM v2: 128x128 tile, 8x8 microtile, K=128 ----------------
// flags: bit0 accumulate; bit1 scale A rows by 1/max(cnt[row/8],1); bit2 bias gated by cnt>0
__global__ __launch_bounds__(256) void sgemm_k128_v2(
    const float* __restrict__ A, const float* __restrict__ B,
    const float* __restrict__ bias, const int* __restrict__ cnt,
    float* __restrict__ C, int Nn, float alpha, int flags)
{
    __shared__ float As[16][132];
    __shared__ float Bs[16][132];
    const int tid = threadIdx.x;
    const int bm = blockIdx.x * 128;
    const int bn = blockIdx.y * 128;
    const int tx = tid & 15;        // N dir, cols tx*8
    const int ty = tid >> 4;        // M dir, rows ty*8

    // A loader: rows ar and ar+64, k-segment ak..ak+3
    const int ar = tid >> 2;
    const int ak = (tid & 3) * 4;
    float rs0 = 1.f, rs1 = 1.f;
    if (flags & 2) {
        int c0 = cnt[(bm + ar) >> 3];       rs0 = 1.f / (float)(c0 > 1 ? c0 : 1);
        int c1 = cnt[(bm + ar + 64) >> 3];  rs1 = 1.f / (float)(c1 > 1 ? c1 : 1);
    }
    const float* Ap0 = A + (size_t)(bm + ar) * 128 + ak;
    const float* Ap1 = Ap0 + (size_t)64 * 128;

    // B loader: rows br and br+8, cols bc..bc+3
    const int br = tid >> 5;
    const int bc = (tid & 31) * 4;
    const float* Bp = B + (size_t)br * Nn + bn + bc;

    float acc[8][8];
    #pragma unroll
    for (int i = 0; i < 8; i++)
        #pragma unroll
        for (int j = 0; j < 8; j++) acc[i][j] = 0.f;

    float4 pa0 = *(const float4*)(Ap0);
    float4 pa1 = *(const float4*)(Ap1);
    float4 pb0 = *(const float4*)(Bp);
    float4 pb1 = *(const float4*)(Bp + (size_t)8 * Nn);

    #pragma unroll 1
    for (int k0 = 0; k0 < 128; k0 += 16) {
        As[ak + 0][ar] = pa0.x * rs0; As[ak + 1][ar] = pa0.y * rs0;
        As[ak + 2][ar] = pa0.z * rs0; As[ak + 3][ar] = pa0.w * rs0;
        As[ak + 0][ar + 64] = pa1.x * rs1; As[ak + 1][ar + 64] = pa1.y * rs1;
        As[ak + 2][ar + 64] = pa1.z * rs1; As[ak + 3][ar + 64] = pa1.w * rs1;
        *(float4*)&Bs[br][bc]     = pb0;
        *(float4*)&Bs[br + 8][bc] = pb1;
        __syncthreads();

        if (k0 < 112) {
            pa0 = *(const float4*)(Ap0 + k0 + 16);
            pa1 = *(const float4*)(Ap1 + k0 + 16);
            pb0 = *(const float4*)(Bp + (size_t)(k0 + 16) * Nn);
            pb1 = *(const float4*)(Bp + (size_t)(k0 + 24) * Nn);
        }

        #pragma unroll
        for (int k = 0; k < 16; k++) {
            float a[8], b[8];
            *(float4*)(a)     = *(const float4*)&As[k][ty * 8];
            *(float4*)(a + 4) = *(const float4*)&As[k][ty * 8 + 4];
            *(float4*)(b)     = *(const float4*)&Bs[k][tx * 8];
            *(float4*)(b + 4) = *(const float4*)&Bs[k][tx * 8 + 4];
            #pragma unroll
            for (int i = 0; i < 8; i++)
                #pragma unroll
                for (int j = 0; j < 8; j++)
                    acc[i][j] += a[i] * b[j];
        }
        __syncthreads();
    }

    float bv[8];
    #pragma unroll
    for (int j = 0; j < 8; j++) bv[j] = bias ? bias[bn + tx * 8 + j] : 0.f;

    #pragma unroll
    for (int i = 0; i < 8; i++) {
        int row = bm + ty * 8 + i;
        float ind = 1.0f;
        if (flags & 4) ind = (cnt[row >> 3] > 0) ? 1.0f : 0.0f;
        float* cp = C + (size_t)row * Nn + bn + tx * 8;
        if (flags & 1) {
            float4 o0 = *(float4*)cp;
            float4 o1 = *(float4*)(cp + 4);
            o0.x += alpha * (acc[i][0] + bv[0] * ind);
            o0.y += alpha * (acc[i][1] + bv[1] * ind);
            o0.z += alpha * (acc[i][2] + bv[2] * ind);
            o0.w += alpha * (acc[i][3] + bv[3] * ind);
            o1.x += alpha * (acc[i][4] + bv[4] * ind);
            o1.y += alpha * (acc[i][5] + bv[5] * ind);
            o1.z += alpha * (acc[i][6] + bv[6] * ind);
            o1.w += alpha * (acc[i][7] + bv[7] * ind);
            *(float4*)cp = o0; *(float4*)(cp + 4) = o1;
        } else {
            float4 o0, o1;
            o0.x = alpha * (acc[i][0] + bv[0] * ind);
            o0.y = alpha * (acc[i][1] + bv[1] * ind);
            o0.z = alpha * (acc[i][2] + bv[2] * ind);
            o0.w = alpha * (acc[i][3] + bv[3] * ind);
            o1.x = alpha * (acc[i][4] + bv[4] * ind);
            o1.y = alpha * (acc[i][5] + bv[5] * ind);
            o1.z = alpha * (acc[i][6] + bv[6] * ind);
            o1.w = alpha * (acc[i][7] + bv[7] * ind);
            *(float4*)cp = o0; *(float4*)(cp + 4) = o1;
        }
    }
}

// ---------------- per-node self scores: S[h][i][j] = scale * Q_i . Kd_j ----------------
__global__ __launch_bounds__(256) void self_scores_kernel(
    const float* __restrict__ projD, float* __restrict__ selfS)
{
    __shared__ float sQ[8][132];
    __shared__ float sK[8][132];
    const int n = blockIdx.x;
    const int tid = threadIdx.x;
    {
        int r = tid >> 5, c = (tid & 31) * 4;
        const float* base = projD + (size_t)n * 8 * 384 + r * 384;
        *(float4*)&sQ[r][c] = *(const float4*)(base + c);
        *(float4*)&sK[r][c] = *(const float4*)(base + 128 + c);
    }
    __syncthreads();
    const int h = tid >> 6;
    const int i = (tid >> 3) & 7;
    const int j = tid & 7;
    const int c0 = h * 32;
    float s = 0.f;
    #pragma unroll
    for (int d = 0; d < 32; d++) s += sQ[i][c0 + d] * sK[j][c0 + d];
    selfS[(size_t)n * 256 + tid] = s * 0.17677669529663687f;  // 1/sqrt(32)
}

// ---------------- per-edge attention + scatter-sum ----------------
// One block per edge, 4 warps = 4 heads. Keys 0..7 = dst self (scores from table),
// keys 8..15 = source. lane = i*4 + p: i = query row, p = key group / 8-dim out slice.
__global__ __launch_bounds__(128) void edge_attn_kernel(
    const int* __restrict__ ei,
    const float* __restrict__ projD, const float* __restrict__ projS,
    const float* __restrict__ selfS,
    float* __restrict__ sumO)
{
    __shared__ float sQ [8][132];
    __shared__ float sVd[8][132];
    __shared__ float sKs[8][132];
    __shared__ float sVs[8][132];
    __shared__ float sS[256];
    const int e   = blockIdx.x;
    const int src = ei[e];
    const int dst = ei[E_EDGES + e];
    const int tid = threadIdx.x;

    {
        const float* dbase = projD + (size_t)dst * 8 * 384;
        const float* sbase = projS + (size_t)src * 8 * 256;
        #pragma unroll
        for (int idx = tid; idx < 256; idx += 128) {
            int r = idx >> 5, c = (idx & 31) << 2;
            *(float4*)&sQ [r][c] = *(const float4*)(dbase + r * 384 + c);
            *(float4*)&sVd[r][c] = *(const float4*)(dbase + r * 384 + 256 + c);
            *(float4*)&sKs[r][c] = *(const float4*)(sbase + r * 256 + c);
            *(float4*)&sVs[r][c] = *(const float4*)(sbase + r * 256 + 128 + c);
        }
        if (tid < 64)
            *(float4*)&sS[tid << 2] = *(const float4*)(selfS + (size_t)dst * 256 + (tid << 2));
    }
    __syncthreads();

    const int h    = tid >> 5;
    const int lane = tid & 31;
    const int i    = lane >> 2;
    const int p    = lane & 3;
    const int c0   = h * 32;

    float q[32];
    #pragma unroll
    for (int d4 = 0; d4 < 8; d4++)
        *(float4*)&q[d4 * 4] = *(const float4*)&sQ[i][c0 + d4 * 4];

    // cross scores for source keys 2p, 2p+1
    const float scale = 0.17677669529663687f;
    float s0 = 0.f, s1 = 0.f;
    {
        const float* k0p = &sKs[2 * p][c0];
        const float* k1p = &sKs[2 * p + 1][c0];
        #pragma unroll
        for (int d = 0; d < 32; d++) { s0 += q[d] * k0p[d]; s1 += q[d] * k1p[d]; }
        s0 *= scale; s1 *= scale;
    }

    // lane p owns keys 4p..4p+3 (0..7 self from table, 8..15 cross via shfl)
    float sc[4];
    #pragma unroll
    for (int j = 0; j < 4; j++) {
        int srcLane = (i << 2) + (((p - 2) & 1) << 1) + (j >> 1);
        float c0v = __shfl_sync(0xffffffffu, s0, srcLane);
        float c1v = __shfl_sync(0xffffffffu, s1, srcLane);
        float cross = (j & 1) ? c1v : c0v;
        sc[j] = (p < 2) ? sS[h * 64 + i * 8 + p * 4 + j] : cross;
    }

    // softmax over 16 keys spread across the 4 lanes of this query group
    float m = fmaxf(fmaxf(sc[0], sc[1]), fmaxf(sc[2], sc[3]));
    m = fmaxf(m, __shfl_xor_sync(0xffffffffu, m, 1));
    m = fmaxf(m, __shfl_xor_sync(0xffffffffu, m, 2));
    float ev[4]; float Z = 0.f;
    #pragma unroll
    for (int j = 0; j < 4; j++) { ev[j] = __expf(sc[j] - m); Z += ev[j]; }
    Z += __shfl_xor_sync(0xffffffffu, Z, 1);
    Z += __shfl_xor_sync(0xffffffffu, Z, 2);

    // output: this lane owns dims [c0 + 8p, c0 + 8p + 8)
    const int d0 = c0 + (p << 3);
    float o[8];
    #pragma unroll
    for (int d = 0; d < 8; d++) o[d] = 0.f;

    #pragma unroll
    for (int x = 0; x < 4; x++) {
        #pragma unroll
        for (int j = 0; j < 4; j++) {
            float ecur = (x == 0) ? ev[j] : __shfl_xor_sync(0xffffffffu, ev[j], x);
            int key = ((p ^ x) << 2) + j;  // 0..15
            const float* vrow = (key < 8) ? &sVd[key][d0] : &sVs[key - 8][d0];
            float4 va = *(const float4*)vrow;
            float4 vb = *(const float4*)(vrow + 4);
            o[0] += ecur * va.x; o[1] += ecur * va.y;
            o[2] += ecur * va.z; o[3] += ecur * va.w;
            o[4] += ecur * vb.x; o[5] += ecur * vb.y;
            o[6] += ecur * vb.z; o[7] += ecur * vb.w;
        }
    }

    float invZ = 1.0f / Z;
    float* outp = sumO + ((size_t)dst * 8 + i) * 128 + d0;
    asm volatile("red.global.add.v4.f32 [%0], {%1, %2, %3, %4};" ::
                 "l"(outp), "f"(o[0] * invZ), "f"(o[1] * invZ),
                 "f"(o[2] * invZ), "f"(o[3] * invZ) : "memory");
    asm volatile("red.global.add.v4.f32 [%0], {%1, %2, %3, %4};" ::
                 "l"(outp + 4), "f"(o[4] * invZ), "f"(o[5] * invZ),
                 "f"(o[6] * invZ), "f"(o[7] * invZ) : "memory");
}

// ---------------- launch ----------------
extern "C" void kernel_launch(void* const* d_in, const int* in_sizes, int n_in,
                              void* d_out, int out_size)
{
    const float* x_a = (const float*)d_in[0];
    const float* x_b = (const float*)d_in[1];
    const int* ei[3] = {(const int*)d_in[2], (const int*)d_in[3], (const int*)d_in[4]};
    const float *Wb[3], *bb[3], *Win[3], *bin[3], *Wo[3], *bo[3];
    for (int r = 0; r < 3; r++) {
        Wb[r]  = (const float*)d_in[5 + 6 * r];
        bb[r]  = (const float*)d_in[6 + 6 * r];
        Win[r] = (const float*)d_in[7 + 6 * r];
        bin[r] = (const float*)d_in[8 + 6 * r];
        Wo[r]  = (const float*)d_in[9 + 6 * r];
        bo[r]  = (const float*)d_in[10 + 6 * r];
    }

    float *projD, *projS, *sumO, *selfS, *WT, *WTs, *bS, *WoT; int* cnt;
    cudaGetSymbolAddress((void**)&projD, g_projD);
    cudaGetSymbolAddress((void**)&projS, g_projS);
    cudaGetSymbolAddress((void**)&sumO,  g_sumO);
    cudaGetSymbolAddress((void**)&selfS, g_selfS);
    cudaGetSymbolAddress((void**)&cnt,   g_cnt);
    cudaGetSymbolAddress((void**)&WT,    g_WT);
    cudaGetSymbolAddress((void**)&WTs,   g_WTs);
    cudaGetSymbolAddress((void**)&bS,    g_bS);
    cudaGetSymbolAddress((void**)&WoT,   g_WoT);

    float* outA = (float*)d_out;
    float* outB = (float*)d_out + (size_t)NS * 128;

    const float* xs[3]  = {x_a, x_b, x_a};
    const float* xd[3]  = {x_b, x_a, x_a};
    float*       op[3]  = {outB, outA, outA};
    const float  al[3]  = {1.0f, 0.5f, 0.5f};
    const int    ac[3]  = {0, 0, 1};

    for (int r = 0; r < 3; r++) {
        cudaMemsetAsync(cnt, 0, N_NODES * sizeof(int), 0);
        count_kernel<<<(E_EDGES + 255) / 256, 256>>>(ei[r] + E_EDGES, cnt);

        transpose_w_kernel<<<(384 * 128 + 255) / 256, 256>>>(Win[r], WT, 384);
        combine_src_kernel<<<128, 128>>>(Win[r], bin[r], Wb[r], bb[r], WTs, bS);
        transpose_w_kernel<<<(128 * 128 + 255) / 256, 256>>>(Wo[r], WoT, 128);

        {   // dst projections: Q | Kd | Vd
            dim3 g(NS / 128, 384 / 128);
            sgemm_k128_v2<<<g, 256>>>(xd[r], WT, bin[r], nullptr, projD, 384, 1.0f, 0);
        }
        {   // src projections: Ks | Vs (Wb folded)
            dim3 g(NS / 128, 256 / 128);
            sgemm_k128_v2<<<g, 256>>>(xs[r], WTs, bS, nullptr, projS, 256, 1.0f, 0);
        }

        self_scores_kernel<<<N_NODES, 256>>>(projD, selfS);

        cudaMemsetAsync(sumO, 0, (size_t)NS * 128 * sizeof(float), 0);
        edge_attn_kernel<<<E_EDGES, 128>>>(ei[r], projD, projS, selfS, sumO);

        {   // mean + Wo + gated bias, scaled/accumulated into output
            dim3 g(NS / 128, 128 / 128);
            sgemm_k128_v2<<<g, 256>>>(sumO, WoT, bo[r], cnt, op[r], 128, al[r],
                                      ac[r] | 2 | 4);
        }
    }
}

// round 11
// speedup vs baseline: 2.5845x; 1.7151x over previous
#include <cuda_runtime.h>
#include <math.h>
#include <stdint.h>

#define N_NODES 20000
#define S_TOK   8
#define D_DIM   128
#define E_EDGES 100000
#define NS      (N_NODES * S_TOK)   // 160000 rows

// ---------------- static scratch (no allocs allowed) ----------------
__device__ float g_projD[(size_t)NS * 384];   // per-dst-node Q|Kd|Vd
__device__ float g_projS[(size_t)NS * 256];   // per-src-node Ks|Vs
__device__ float g_sumO [(size_t)NS * 128];   // attention-output accum
__device__ float g_selfS[(size_t)N_NODES * 256]; // per-node self scores [h][i][j]
__device__ int   g_cnt  [N_NODES];
__device__ float g_WT   [128 * 384];          // Win transposed [K, 3D]
__device__ float g_WTs  [128 * 256];          // combined (Wk*Wb | Wv*Wb) transposed
__device__ float g_bS   [256];                // combined src biases
__device__ float g_WoT  [128 * 128];          // Wo transposed

// ---------------- helpers ----------------
__device__ __forceinline__ float to_tf32(float x) {
    float r; asm("cvt.rna.tf32.f32 %0, %1;" : "=f"(r) : "f"(x)); return r;
}
__device__ __forceinline__ void mma_tf32(float* c, const uint32_t* a, const uint32_t* b) {
    asm volatile("mma.sync.aligned.m16n8k8.row.col.f32.tf32.tf32.f32 "
        "{%0,%1,%2,%3}, {%4,%5,%6,%7}, {%8,%9}, {%0,%1,%2,%3};"
        : "+f"(c[0]), "+f"(c[1]), "+f"(c[2]), "+f"(c[3])
        : "r"(a[0]), "r"(a[1]), "r"(a[2]), "r"(a[3]), "r"(b[0]), "r"(b[1]));
}

// ---------------- counts ----------------
__global__ void count_kernel(const int* __restrict__ dst, int* __restrict__ cnt) {
    int e = blockIdx.x * blockDim.x + threadIdx.x;
    if (e < E_EDGES) atomicAdd(&cnt[dst[e]], 1);
}

// ---------------- weight prep ----------------
__global__ void transpose_w_kernel(const float* __restrict__ W, float* __restrict__ WT, int rows) {
    int idx = blockIdx.x * blockDim.x + threadIdx.x;
    if (idx < rows * 128) {
        int k = idx / rows, o = idx % rows;
        WT[idx] = W[o * 128 + k];
    }
}

__global__ void combine_src_kernel(const float* __restrict__ Win, const float* __restrict__ binp,
                                   const float* __restrict__ Wb,  const float* __restrict__ bb,
                                   float* __restrict__ WTs, float* __restrict__ bS) {
    int o = blockIdx.x;   // 0..127
    int k = threadIdx.x;  // 0..127
    const float* wkrow = Win + (128 + o) * 128;
    const float* wvrow = Win + (256 + o) * 128;
    float sk = 0.f, sv = 0.f;
    for (int j = 0; j < 128; j++) {
        float wb = Wb[j * 128 + k];
        sk += wkrow[j] * wb;
        sv += wvrow[j] * wb;
    }
    WTs[k * 256 + o]       = sk;
    WTs[k * 256 + 128 + o] = sv;
    if (k == 0) {
        float s = 0.f;
        for (int j = 0; j < 128; j++) s += wkrow[j] * bb[j];
        bS[o] = s + binp[128 + o];
    } else if (k == 1) {
        float s = 0.f;
        for (int j = 0; j < 128; j++) s += wvrow[j] * bb[j];
        bS[128 + o] = s + binp[256 + o];
    }
}

// ---------------- tf32 tensor-core GEMM: C[M,Nn] = alpha*(A[M,128]@B[128,Nn] + bias*ind) ----------------
// flags: bit0 accumulate; bit1 scale A rows by 1/max(cnt[row/8],1); bit2 bias gated by cnt>0
// Block 128x128, 8 warps (4x2), warp tile 32x64, m16n8k8 fragments, K-chunk 16 double-buffered.
__global__ __launch_bounds__(256, 2) void gemm_tf32(
    const float* __restrict__ A, const float* __restrict__ B,
    const float* __restrict__ bias, const int* __restrict__ cnt,
    float* __restrict__ C, int Nn, float alpha, int flags)
{
    __shared__ float As[2][128][20];   // stride 20: frag banks 20g+tg all distinct
    __shared__ float Bs[2][16][136];   // stride 136: frag banks 8tg+g all distinct
    const int tid = threadIdx.x;
    const int bm = blockIdx.x * 128;
    const int bn = blockIdx.y * 128;
    const int wid = tid >> 5, lane = tid & 31;
    const int wm = (wid & 3) * 32;
    const int wn = (wid >> 2) * 64;
    const int g  = lane >> 2, tg = lane & 3;

    // A loader: rows ar, ar+64; k-seg ac..ac+3
    const int ar = tid >> 2;
    const int ac = (tid & 3) * 4;
    float rs0 = 1.f, rs1 = 1.f;
    if (flags & 2) {
        int c0 = cnt[(bm + ar) >> 3];       rs0 = 1.f / (float)(c0 > 1 ? c0 : 1);
        int c1 = cnt[(bm + ar + 64) >> 3];  rs1 = 1.f / (float)(c1 > 1 ? c1 : 1);
    }
    const float* Ap = A + (size_t)(bm + ar) * 128 + ac;
    // B loader: rows br, br+8; cols bc..bc+3
    const int br = tid >> 5;
    const int bc = (tid & 31) * 4;
    const float* Bp = B + (size_t)br * Nn + bn + bc;

    float acc[2][8][4];
    #pragma unroll
    for (int mt = 0; mt < 2; mt++)
        #pragma unroll
        for (int nt = 0; nt < 8; nt++)
            #pragma unroll
            for (int j = 0; j < 4; j++) acc[mt][nt][j] = 0.f;

    float4 ra0 = *(const float4*)(Ap);
    float4 ra1 = *(const float4*)(Ap + (size_t)64 * 128);
    float4 rb0 = *(const float4*)(Bp);
    float4 rb1 = *(const float4*)(Bp + (size_t)8 * Nn);

    #pragma unroll 1
    for (int ch = 0; ch < 8; ch++) {
        const int bsel = ch & 1;
        As[bsel][ar][ac + 0]      = to_tf32(ra0.x * rs0);
        As[bsel][ar][ac + 1]      = to_tf32(ra0.y * rs0);
        As[bsel][ar][ac + 2]      = to_tf32(ra0.z * rs0);
        As[bsel][ar][ac + 3]      = to_tf32(ra0.w * rs0);
        As[bsel][ar + 64][ac + 0] = to_tf32(ra1.x * rs1);
        As[bsel][ar + 64][ac + 1] = to_tf32(ra1.y * rs1);
        As[bsel][ar + 64][ac + 2] = to_tf32(ra1.z * rs1);
        As[bsel][ar + 64][ac + 3] = to_tf32(ra1.w * rs1);
        Bs[bsel][br][bc + 0]      = to_tf32(rb0.x);
        Bs[bsel][br][bc + 1]      = to_tf32(rb0.y);
        Bs[bsel][br][bc + 2]      = to_tf32(rb0.z);
        Bs[bsel][br][bc + 3]      = to_tf32(rb0.w);
        Bs[bsel][br + 8][bc + 0]  = to_tf32(rb1.x);
        Bs[bsel][br + 8][bc + 1]  = to_tf32(rb1.y);
        Bs[bsel][br + 8][bc + 2]  = to_tf32(rb1.z);
        Bs[bsel][br + 8][bc + 3]  = to_tf32(rb1.w);
        __syncthreads();

        if (ch < 7) {
            const int k0 = (ch + 1) * 16;
            ra0 = *(const float4*)(Ap + k0);
            ra1 = *(const float4*)(Ap + (size_t)64 * 128 + k0);
            rb0 = *(const float4*)(Bp + (size_t)k0 * Nn);
            rb1 = *(const float4*)(Bp + (size_t)(k0 + 8) * Nn);
        }

        #pragma unroll
        for (int kk = 0; kk < 2; kk++) {
            uint32_t af[2][4], bf[8][2];
            #pragma unroll
            for (int mt = 0; mt < 2; mt++) {
                const float* a0p = &As[bsel][wm + mt * 16 + g][kk * 8 + tg];
                const float* a1p = &As[bsel][wm + mt * 16 + g + 8][kk * 8 + tg];
                af[mt][0] = __float_as_uint(a0p[0]);
                af[mt][1] = __float_as_uint(a1p[0]);
                af[mt][2] = __float_as_uint(a0p[4]);
                af[mt][3] = __float_as_uint(a1p[4]);
            }
            #pragma unroll
            for (int nt = 0; nt < 8; nt++) {
                bf[nt][0] = __float_as_uint(Bs[bsel][kk * 8 + tg][wn + nt * 8 + g]);
                bf[nt][1] = __float_as_uint(Bs[bsel][kk * 8 + 4 + tg][wn + nt * 8 + g]);
            }
            #pragma unroll
            for (int mt = 0; mt < 2; mt++)
                #pragma unroll
                for (int nt = 0; nt < 8; nt++)
                    mma_tf32(acc[mt][nt], af[mt], bf[nt]);
        }
    }

    // epilogue
    #pragma unroll
    for (int mt = 0; mt < 2; mt++) {
        #pragma unroll
        for (int ri = 0; ri < 2; ri++) {
            const int row = bm + wm + mt * 16 + g + ri * 8;
            float ind = 1.0f;
            if (flags & 4) ind = (cnt[row >> 3] > 0) ? 1.0f : 0.0f;
            float* cp = C + (size_t)row * Nn + bn + wn + tg * 2;
            #pragma unroll
            for (int nt = 0; nt < 8; nt++) {
                float b0 = 0.f, b1 = 0.f;
                if (bias) {
                    b0 = bias[bn + wn + nt * 8 + tg * 2 + 0];
                    b1 = bias[bn + wn + nt * 8 + tg * 2 + 1];
                }
                float v0 = alpha * (acc[mt][nt][ri * 2 + 0] + b0 * ind);
                float v1 = alpha * (acc[mt][nt][ri * 2 + 1] + b1 * ind);
                float2 o;
                if (flags & 1) {
                    float2 old = *(float2*)(cp + nt * 8);
                    o.x = old.x + v0; o.y = old.y + v1;
                } else {
                    o.x = v0; o.y = v1;
                }
                *(float2*)(cp + nt * 8) = o;
            }
        }
    }
}

// ---------------- per-node self scores: S[h][i][j] = scale * Q_i . Kd_j ----------------
__global__ __launch_bounds__(256) void self_scores_kernel(
    const float* __restrict__ projD, float* __restrict__ selfS)
{
    __shared__ float sQ[8][132];
    __shared__ float sK[8][132];
    const int n = blockIdx.x;
    const int tid = threadIdx.x;
    {
        int r = tid >> 5, c = (tid & 31) * 4;
        const float* base = projD + (size_t)n * 8 * 384 + r * 384;
        *(float4*)&sQ[r][c] = *(const float4*)(base + c);
        *(float4*)&sK[r][c] = *(const float4*)(base + 128 + c);
    }
    __syncthreads();
    const int h = tid >> 6;
    const int i = (tid >> 3) & 7;
    const int j = tid & 7;
    const int c0 = h * 32;
    float s = 0.f;
    #pragma unroll
    for (int d = 0; d < 32; d++) s += sQ[i][c0 + d] * sK[j][c0 + d];
    selfS[(size_t)n * 256 + tid] = s * 0.17677669529663687f;  // 1/sqrt(32)
}

// ---------------- per-edge attention + scatter-sum ----------------
__global__ __launch_bounds__(128) void edge_attn_kernel(
    const int* __restrict__ ei,
    const float* __restrict__ projD, const float* __restrict__ projS,
    const float* __restrict__ selfS,
    float* __restrict__ sumO)
{
    __shared__ float sQ [8][132];
    __shared__ float sVd[8][132];
    __shared__ float sKs[8][132];
    __shared__ float sVs[8][132];
    __shared__ float sS[256];
    const int e   = blockIdx.x;
    const int src = ei[e];
    const int dst = ei[E_EDGES + e];
    const int tid = threadIdx.x;

    {
        const float* dbase = projD + (size_t)dst * 8 * 384;
        const float* sbase = projS + (size_t)src * 8 * 256;
        #pragma unroll
        for (int idx = tid; idx < 256; idx += 128) {
            int r = idx >> 5, c = (idx & 31) << 2;
            *(float4*)&sQ [r][c] = *(const float4*)(dbase + r * 384 + c);
            *(float4*)&sVd[r][c] = *(const float4*)(dbase + r * 384 + 256 + c);
            *(float4*)&sKs[r][c] = *(const float4*)(sbase + r * 256 + c);
            *(float4*)&sVs[r][c] = *(const float4*)(sbase + r * 256 + 128 + c);
        }
        if (tid < 64)
            *(float4*)&sS[tid << 2] = *(const float4*)(selfS + (size_t)dst * 256 + (tid << 2));
    }
    __syncthreads();

    const int h    = tid >> 5;
    const int lane = tid & 31;
    const int i    = lane >> 2;
    const int p    = lane & 3;
    const int c0   = h * 32;

    float q[32];
    #pragma unroll
    for (int d4 = 0; d4 < 8; d4++)
        *(float4*)&q[d4 * 4] = *(const float4*)&sQ[i][c0 + d4 * 4];

    const float scale = 0.17677669529663687f;
    float s0 = 0.f, s1 = 0.f;
    {
        const float* k0p = &sKs[2 * p][c0];
        const float* k1p = &sKs[2 * p + 1][c0];
        #pragma unroll
        for (int d = 0; d < 32; d++) { s0 += q[d] * k0p[d]; s1 += q[d] * k1p[d]; }
        s0 *= scale; s1 *= scale;
    }

    float sc[4];
    #pragma unroll
    for (int j = 0; j < 4; j++) {
        int srcLane = (i << 2) + (((p - 2) & 1) << 1) + (j >> 1);
        float c0v = __shfl_sync(0xffffffffu, s0, srcLane);
        float c1v = __shfl_sync(0xffffffffu, s1, srcLane);
        float cross = (j & 1) ? c1v : c0v;
        sc[j] = (p < 2) ? sS[h * 64 + i * 8 + p * 4 + j] : cross;
    }

    float m = fmaxf(fmaxf(sc[0], sc[1]), fmaxf(sc[2], sc[3]));
    m = fmaxf(m, __shfl_xor_sync(0xffffffffu, m, 1));
    m = fmaxf(m, __shfl_xor_sync(0xffffffffu, m, 2));
    float ev[4]; float Z = 0.f;
    #pragma unroll
    for (int j = 0; j < 4; j++) { ev[j] = __expf(sc[j] - m); Z += ev[j]; }
    Z += __shfl_xor_sync(0xffffffffu, Z, 1);
    Z += __shfl_xor_sync(0xffffffffu, Z, 2);

    const int d0 = c0 + (p << 3);
    float o[8];
    #pragma unroll
    for (int d = 0; d < 8; d++) o[d] = 0.f;

    #pragma unroll
    for (int x = 0; x < 4; x++) {
        #pragma unroll
        for (int j = 0; j < 4; j++) {
            float ecur = (x == 0) ? ev[j] : __shfl_xor_sync(0xffffffffu, ev[j], x);
            int key = ((p ^ x) << 2) + j;  // 0..15
            const float* vrow = (key < 8) ? &sVd[key][d0] : &sVs[key - 8][d0];
            float4 va = *(const float4*)vrow;
            float4 vb = *(const float4*)(vrow + 4);
            o[0] += ecur * va.x; o[1] += ecur * va.y;
            o[2] += ecur * va.z; o[3] += ecur * va.w;
            o[4] += ecur * vb.x; o[5] += ecur * vb.y;
            o[6] += ecur * vb.z; o[7] += ecur * vb.w;
        }
    }

    float invZ = 1.0f / Z;
    float* outp = sumO + ((size_t)dst * 8 + i) * 128 + d0;
    asm volatile("red.global.add.v4.f32 [%0], {%1, %2, %3, %4};" ::
                 "l"(outp), "f"(o[0] * invZ), "f"(o[1] * invZ),
                 "f"(o[2] * invZ), "f"(o[3] * invZ) : "memory");
    asm volatile("red.global.add.v4.f32 [%0], {%1, %2, %3, %4};" ::
                 "l"(outp + 4), "f"(o[4] * invZ), "f"(o[5] * invZ),
                 "f"(o[6] * invZ), "f"(o[7] * invZ) : "memory");
}

// ---------------- launch ----------------
extern "C" void kernel_launch(void* const* d_in, const int* in_sizes, int n_in,
                              void* d_out, int out_size)
{
    const float* x_a = (const float*)d_in[0];
    const float* x_b = (const float*)d_in[1];
    const int* ei[3] = {(const int*)d_in[2], (const int*)d_in[3], (const int*)d_in[4]};
    const float *Wb[3], *bb[3], *Win[3], *bin[3], *Wo[3], *bo[3];
    for (int r = 0; r < 3; r++) {
        Wb[r]  = (const float*)d_in[5 + 6 * r];
        bb[r]  = (const float*)d_in[6 + 6 * r];
        Win[r] = (const float*)d_in[7 + 6 * r];
        bin[r] = (const float*)d_in[8 + 6 * r];
        Wo[r]  = (const float*)d_in[9 + 6 * r];
        bo[r]  = (const float*)d_in[10 + 6 * r];
    }

    float *projD, *projS, *sumO, *selfS, *WT, *WTs, *bS, *WoT; int* cnt;
    cudaGetSymbolAddress((void**)&projD, g_projD);
    cudaGetSymbolAddress((void**)&projS, g_projS);
    cudaGetSymbolAddress((void**)&sumO,  g_sumO);
    cudaGetSymbolAddress((void**)&selfS, g_selfS);
    cudaGetSymbolAddress((void**)&cnt,   g_cnt);
    cudaGetSymbolAddress((void**)&WT,    g_WT);
    cudaGetSymbolAddress((void**)&WTs,   g_WTs);
    cudaGetSymbolAddress((void**)&bS,    g_bS);
    cudaGetSymbolAddress((void**)&WoT,   g_WoT);

    float* outA = (float*)d_out;
    float* outB = (float*)d_out + (size_t)NS * 128;

    const float* xs[3]  = {x_a, x_b, x_a};
    const float* xd[3]  = {x_b, x_a, x_a};
    float*       op[3]  = {outB, outA, outA};
    const float  al[3]  = {1.0f, 0.5f, 0.5f};
    const int    ac[3]  = {0, 0, 1};

    for (int r = 0; r < 3; r++) {
        cudaMemsetAsync(cnt, 0, N_NODES * sizeof(int), 0);
        count_kernel<<<(E_EDGES + 255) / 256, 256>>>(ei[r] + E_EDGES, cnt);

        transpose_w_kernel<<<(384 * 128 + 255) / 256, 256>>>(Win[r], WT, 384);
        combine_src_kernel<<<128, 128>>>(Win[r], bin[r], Wb[r], bb[r], WTs, bS);
        transpose_w_kernel<<<(128 * 128 + 255) / 256, 256>>>(Wo[r], WoT, 128);

        {   // dst projections: Q | Kd | Vd
            dim3 g(NS / 128, 384 / 128);
            gemm_tf32<<<g, 256>>>(xd[r], WT, bin[r], nullptr, projD, 384, 1.0f, 0);
        }
        {   // src projections: Ks | Vs (Wb folded)
            dim3 g(NS / 128, 256 / 128);
            gemm_tf32<<<g, 256>>>(xs[r], WTs, bS, nullptr, projS, 256, 1.0f, 0);
        }

        self_scores_kernel<<<N_NODES, 256>>>(projD, selfS);

        cudaMemsetAsync(sumO, 0, (size_t)NS * 128 * sizeof(float), 0);
        edge_attn_kernel<<<E_EDGES, 128>>>(ei[r], projD, projS, selfS, sumO);

        {   // mean + Wo + gated bias, scaled/accumulated into output
            dim3 g(NS / 128, 128 / 128);
            gemm_tf32<<<g, 256>>>(sumO, WoT, bo[r], cnt, op[r], 128, al[r],
                                  ac[r] | 2 | 4);
        }
    }
}

// round 14
// speedup vs baseline: 3.0331x; 1.1736x over previous
#include <cuda_runtime.h>
#include <math.h>
#include <stdint.h>

#define N_NODES 20000
#define S_TOK   8
#define D_DIM   128
#define E_EDGES 100000
#define NS      (N_NODES * S_TOK)   // 160000 rows

// ---------------- static scratch (no allocs allowed) ----------------
__device__ float g_projD[(size_t)NS * 384];   // per-dst-node Q|Kd|Vd
__device__ float g_projS[(size_t)NS * 256];   // per-src-node Ks|Vs
__device__ float g_sumO [(size_t)NS * 128];   // attention-output accum
__device__ int   g_cnt  [N_NODES];
__device__ int   g_off  [N_NODES + 1];
__device__ int   g_cursor[N_NODES];
__device__ int   g_srcList[E_EDGES];
__device__ float g_WT   [128 * 384];          // Win transposed [K, 3D]
__device__ float g_WTs  [128 * 256];          // combined (Wk*Wb | Wv*Wb) transposed
__device__ float g_bS   [256];                // combined src biases
__device__ float g_WoT  [128 * 128];          // Wo transposed

// ---------------- helpers ----------------
__device__ __forceinline__ float to_tf32(float x) {
    float r; asm("cvt.rna.tf32.f32 %0, %1;" : "=f"(r) : "f"(x)); return r;
}
__device__ __forceinline__ void mma_tf32(float* c, const uint32_t* a, const uint32_t* b) {
    asm volatile("mma.sync.aligned.m16n8k8.row.col.f32.tf32.tf32.f32 "
        "{%0,%1,%2,%3}, {%4,%5,%6,%7}, {%8,%9}, {%0,%1,%2,%3};"
        : "+f"(c[0]), "+f"(c[1]), "+f"(c[2]), "+f"(c[3])
        : "r"(a[0]), "r"(a[1]), "r"(a[2]), "r"(a[3]), "r"(b[0]), "r"(b[1]));
}
__device__ __forceinline__ uint32_t smem_u32(const void* p) {
    return (uint32_t)__cvta_generic_to_shared(p);
}
#define CP_ASYNC16(smem_addr, gptr) \
    asm volatile("cp.async.ca.shared.global [%0], [%1], 16;" :: "r"(smem_addr), "l"(gptr))
#define CP_COMMIT() asm volatile("cp.async.commit_group;")

// ---------------- counts ----------------
__global__ void count_kernel(const int* __restrict__ dst, int* __restrict__ cnt) {
    int e = blockIdx.x * blockDim.x + threadIdx.x;
    if (e < E_EDGES) atomicAdd(&cnt[dst[e]], 1);
}

// ---------------- exclusive scan of cnt -> off (single block, 1024 threads) ----------------
__global__ __launch_bounds__(1024) void scan_kernel(const int* __restrict__ cnt, int* __restrict__ off) {
    __shared__ int warp_sums[32];
    __shared__ int s_carry;
    const int tid = threadIdx.x;
    const int lane = tid & 31, wid = tid >> 5;
    if (tid == 0) s_carry = 0;
    __syncthreads();
    const int nchunks = (N_NODES + 1023) / 1024;
    for (int chunk = 0; chunk < nchunks; chunk++) {
        int idx = chunk * 1024 + tid;
        int v = (idx < N_NODES) ? cnt[idx] : 0;
        int x = v;
        #pragma unroll
        for (int o = 1; o < 32; o <<= 1) {
            int y = __shfl_up_sync(0xffffffffu, x, o);
            if (lane >= o) x += y;
        }
        if (lane == 31) warp_sums[wid] = x;
        __syncthreads();
        if (wid == 0) {
            int w = warp_sums[lane];
            #pragma unroll
            for (int o = 1; o < 32; o <<= 1) {
                int y = __shfl_up_sync(0xffffffffu, w, o);
                if (lane >= o) w += y;
            }
            warp_sums[lane] = w;
        }
        __syncthreads();
        int warp_off = (wid > 0) ? warp_sums[wid - 1] : 0;
        int incl = x + warp_off + s_carry;
        if (idx < N_NODES) off[idx] = incl - v;      // exclusive
        if (idx == N_NODES - 1) off[N_NODES] = incl; // total
        __syncthreads();
        if (tid == 1023) s_carry = incl;
        __syncthreads();
    }
}

// ---------------- scatter edges into dst-sorted src list ----------------
__global__ void fill_kernel(const int* __restrict__ ei, int* __restrict__ cursor,
                            int* __restrict__ srcList) {
    int e = blockIdx.x * blockDim.x + threadIdx.x;
    if (e < E_EDGES) {
        int d = ei[E_EDGES + e];
        int pos = atomicAdd(&cursor[d], 1);
        srcList[pos] = ei[e];
    }
}

// ---------------- weight prep ----------------
__global__ void transpose_w_kernel(const float* __restrict__ W, float* __restrict__ WT, int rows) {
    int idx = blockIdx.x * blockDim.x + threadIdx.x;
    if (idx < rows * 128) {
        int k = idx / rows, o = idx % rows;
        WT[idx] = W[o * 128 + k];
    }
}

__global__ void combine_src_kernel(const float* __restrict__ Win, const float* __restrict__ binp,
                                   const float* __restrict__ Wb,  const float* __restrict__ bb,
                                   float* __restrict__ WTs, float* __restrict__ bS) {
    int o = blockIdx.x;   // 0..127
    int k = threadIdx.x;  // 0..127
    const float* wkrow = Win + (128 + o) * 128;
    const float* wvrow = Win + (256 + o) * 128;
    float sk = 0.f, sv = 0.f;
    for (int j = 0; j < 128; j++) {
        float wb = Wb[j * 128 + k];
        sk += wkrow[j] * wb;
        sv += wvrow[j] * wb;
    }
    WTs[k * 256 + o]       = sk;
    WTs[k * 256 + 128 + o] = sv;
    if (k == 0) {
        float s = 0.f;
        for (int j = 0; j < 128; j++) s += wkrow[j] * bb[j];
        bS[o] = s + binp[128 + o];
    } else if (k == 1) {
        float s = 0.f;
        for (int j = 0; j < 128; j++) s += wvrow[j] * bb[j];
        bS[128 + o] = s + binp[256 + o];
    }
}

// ---------------- tf32 tensor-core GEMM (unchanged from R8/R11) ----------------
__global__ __launch_bounds__(256, 2) void gemm_tf32(
    const float* __restrict__ A, const float* __restrict__ B,
    const float* __restrict__ bias, const int* __restrict__ cnt,
    float* __restrict__ C, int Nn, float alpha, int flags)
{
    __shared__ float As[2][128][20];
    __shared__ float Bs[2][16][136];
    const int tid = threadIdx.x;
    const int bm = blockIdx.x * 128;
    const int bn = blockIdx.y * 128;
    const int wid = tid >> 5, lane = tid & 31;
    const int wm = (wid & 3) * 32;
    const int wn = (wid >> 2) * 64;
    const int g  = lane >> 2, tg = lane & 3;

    const int ar = tid >> 2;
    const int ac = (tid & 3) * 4;
    float rs0 = 1.f, rs1 = 1.f;
    if (flags & 2) {
        int c0 = cnt[(bm + ar) >> 3];       rs0 = 1.f / (float)(c0 > 1 ? c0 : 1);
        int c1 = cnt[(bm + ar + 64) >> 3];  rs1 = 1.f / (float)(c1 > 1 ? c1 : 1);
    }
    const float* Ap = A + (size_t)(bm + ar) * 128 + ac;
    const int br = tid >> 5;
    const int bc = (tid & 31) * 4;
    const float* Bp = B + (size_t)br * Nn + bn + bc;

    float acc[2][8][4];
    #pragma unroll
    for (int mt = 0; mt < 2; mt++)
        #pragma unroll
        for (int nt = 0; nt < 8; nt++)
            #pragma unroll
            for (int j = 0; j < 4; j++) acc[mt][nt][j] = 0.f;

    float4 ra0 = *(const float4*)(Ap);
    float4 ra1 = *(const float4*)(Ap + (size_t)64 * 128);
    float4 rb0 = *(const float4*)(Bp);
    float4 rb1 = *(const float4*)(Bp + (size_t)8 * Nn);

    #pragma unroll 1
    for (int ch = 0; ch < 8; ch++) {
        const int bsel = ch & 1;
        As[bsel][ar][ac + 0]      = to_tf32(ra0.x * rs0);
        As[bsel][ar][ac + 1]      = to_tf32(ra0.y * rs0);
        As[bsel][ar][ac + 2]      = to_tf32(ra0.z * rs0);
        As[bsel][ar][ac + 3]      = to_tf32(ra0.w * rs0);
        As[bsel][ar + 64][ac + 0] = to_tf32(ra1.x * rs1);
        As[bsel][ar + 64][ac + 1] = to_tf32(ra1.y * rs1);
        As[bsel][ar + 64][ac + 2] = to_tf32(ra1.z * rs1);
        As[bsel][ar + 64][ac + 3] = to_tf32(ra1.w * rs1);
        Bs[bsel][br][bc + 0]      = to_tf32(rb0.x);
        Bs[bsel][br][bc + 1]      = to_tf32(rb0.y);
        Bs[bsel][br][bc + 2]      = to_tf32(rb0.z);
        Bs[bsel][br][bc + 3]      = to_tf32(rb0.w);
        Bs[bsel][br + 8][bc + 0]  = to_tf32(rb1.x);
        Bs[bsel][br + 8][bc + 1]  = to_tf32(rb1.y);
        Bs[bsel][br + 8][bc + 2]  = to_tf32(rb1.z);
        Bs[bsel][br + 8][bc + 3]  = to_tf32(rb1.w);
        __syncthreads();

        if (ch < 7) {
            const int k0 = (ch + 1) * 16;
            ra0 = *(const float4*)(Ap + k0);
            ra1 = *(const float4*)(Ap + (size_t)64 * 128 + k0);
            rb0 = *(const float4*)(Bp + (size_t)k0 * Nn);
            rb1 = *(const float4*)(Bp + (size_t)(k0 + 8) * Nn);
        }

        #pragma unroll
        for (int kk = 0; kk < 2; kk++) {
            uint32_t af[2][4], bf[8][2];
            #pragma unroll
            for (int mt = 0; mt < 2; mt++) {
                const float* a0p = &As[bsel][wm + mt * 16 + g][kk * 8 + tg];
                const float* a1p = &As[bsel][wm + mt * 16 + g + 8][kk * 8 + tg];
                af[mt][0] = __float_as_uint(a0p[0]);
                af[mt][1] = __float_as_uint(a1p[0]);
                af[mt][2] = __float_as_uint(a0p[4]);
                af[mt][3] = __float_as_uint(a1p[4]);
            }
            #pragma unroll
            for (int nt = 0; nt < 8; nt++) {
                bf[nt][0] = __float_as_uint(Bs[bsel][kk * 8 + tg][wn + nt * 8 + g]);
                bf[nt][1] = __float_as_uint(Bs[bsel][kk * 8 + 4 + tg][wn + nt * 8 + g]);
            }
            #pragma unroll
            for (int mt = 0; mt < 2; mt++)
                #pragma unroll
                for (int nt = 0; nt < 8; nt++)
                    mma_tf32(acc[mt][nt], af[mt], bf[nt]);
        }
    }

    #pragma unroll
    for (int mt = 0; mt < 2; mt++) {
        #pragma unroll
        for (int ri = 0; ri < 2; ri++) {
            const int row = bm + wm + mt * 16 + g + ri * 8;
            float ind = 1.0f;
            if (flags & 4) ind = (cnt[row >> 3] > 0) ? 1.0f : 0.0f;
            float* cp = C + (size_t)row * Nn + bn + wn + tg * 2;
            #pragma unroll
            for (int nt = 0; nt < 8; nt++) {
                float b0 = 0.f, b1 = 0.f;
                if (bias) {
                    b0 = bias[bn + wn + nt * 8 + tg * 2 + 0];
                    b1 = bias[bn + wn + nt * 8 + tg * 2 + 1];
                }
                float v0 = alpha * (acc[mt][nt][ri * 2 + 0] + b0 * ind);
                float v1 = alpha * (acc[mt][nt][ri * 2 + 1] + b1 * ind);
                float2 o;
                if (flags & 1) {
                    float2 old = *(float2*)(cp + nt * 8);
                    o.x = old.x + v0; o.y = old.y + v1;
                } else {
                    o.x = v0; o.y = v1;
                }
                *(float2*)(cp + nt * 8) = o;
            }
        }
    }
}

// ---------------- per-dst-node aggregation: attention over sorted incoming edges ----------------
// One block per dst node, 4 warps = 4 heads. Q/Kd/Vd loaded once; self-scores computed in
// prologue; per-edge Ks/Vs streamed via double-buffered cp.async; plain stores (no atomics).
__global__ __launch_bounds__(128) void agg_kernel(
    const int* __restrict__ srcList, const int* __restrict__ off,
    const float* __restrict__ projD, const float* __restrict__ projS,
    float* __restrict__ sumO)
{
    __shared__ float sQ [8][132];
    __shared__ float sVd[8][132];
    __shared__ float sKs[2][8][132];
    __shared__ float sVs[2][8][132];
    __shared__ float sS[256];
    const int n   = blockIdx.x;
    const int tid = threadIdx.x;
    const int base = off[n];
    const int deg  = off[n + 1] - base;

    // load Q, Vd; Kd temporarily into sKs[1]
    {
        const float* dbase = projD + (size_t)n * 3072;
        #pragma unroll
        for (int idx = tid; idx < 256; idx += 128) {
            int r = idx >> 5, c = (idx & 31) << 2;
            *(float4*)&sQ [r][c]    = *(const float4*)(dbase + r * 384 + c);
            *(float4*)&sKs[1][r][c] = *(const float4*)(dbase + r * 384 + 128 + c);
            *(float4*)&sVd[r][c]    = *(const float4*)(dbase + r * 384 + 256 + c);
        }
    }
    __syncthreads();

    // prefetch edge 0 into buffer 0 (overlaps with self-score compute)
    if (deg > 0) {
        const float* sbase = projS + (size_t)srcList[base] * 2048;
        #pragma unroll
        for (int idx = tid; idx < 256; idx += 128) {
            int r = idx >> 5, c = (idx & 31) << 2;
            CP_ASYNC16(smem_u32(&sKs[0][r][c]), sbase + r * 256 + c);
            CP_ASYNC16(smem_u32(&sVs[0][r][c]), sbase + r * 256 + 128 + c);
        }
    }
    CP_COMMIT();

    const float scale = 0.17677669529663687f;  // 1/sqrt(32)
    // self scores S[h][i][j] (Kd in sKs[1])
    #pragma unroll
    for (int t = tid; t < 256; t += 128) {
        int hh = t >> 6, ii = (t >> 3) & 7, jj = t & 7;
        const float* qp = &sQ[ii][hh * 32];
        const float* kp = &sKs[1][jj][hh * 32];
        float s = 0.f;
        #pragma unroll
        for (int d = 0; d < 32; d++) s += qp[d] * kp[d];
        sS[t] = s * scale;
    }

    const int h    = tid >> 5;
    const int lane = tid & 31;
    const int i    = lane >> 2;
    const int p    = lane & 3;
    const int c0   = h * 32;
    const int d0   = c0 + (p << 3);

    float q[32];
    #pragma unroll
    for (int d4 = 0; d4 < 8; d4++)
        *(float4*)&q[d4 * 4] = *(const float4*)&sQ[i][c0 + d4 * 4];

    __syncthreads();   // sS visible to all; Kd-temp (sKs[1]) free for reuse

    float acc[8];
    #pragma unroll
    for (int d = 0; d < 8; d++) acc[d] = 0.f;

    #pragma unroll 1
    for (int t = 0; t < deg; t++) {
        const int buf = t & 1;
        if (t + 1 < deg) {
            const float* sbase = projS + (size_t)srcList[base + t + 1] * 2048;
            #pragma unroll
            for (int idx = tid; idx < 256; idx += 128) {
                int r = idx >> 5, c = (idx & 31) << 2;
                CP_ASYNC16(smem_u32(&sKs[buf ^ 1][r][c]), sbase + r * 256 + c);
                CP_ASYNC16(smem_u32(&sVs[buf ^ 1][r][c]), sbase + r * 256 + 128 + c);
            }
        }
        CP_COMMIT();
        asm volatile("cp.async.wait_group 1;");
        __syncthreads();

        // cross scores for source keys 2p, 2p+1
        float s0 = 0.f, s1 = 0.f;
        {
            const float* k0p = &sKs[buf][2 * p][c0];
            const float* k1p = &sKs[buf][2 * p + 1][c0];
            #pragma unroll
            for (int d = 0; d < 32; d++) { s0 += q[d] * k0p[d]; s1 += q[d] * k1p[d]; }
            s0 *= scale; s1 *= scale;
        }

        float sc[4];
        #pragma unroll
        for (int j = 0; j < 4; j++) {
            int srcLane = (i << 2) + (((p - 2) & 1) << 1) + (j >> 1);
            float c0v = __shfl_sync(0xffffffffu, s0, srcLane);
            float c1v = __shfl_sync(0xffffffffu, s1, srcLane);
            float cross = (j & 1) ? c1v : c0v;
            sc[j] = (p < 2) ? sS[h * 64 + i * 8 + p * 4 + j] : cross;
        }

        float m = fmaxf(fmaxf(sc[0], sc[1]), fmaxf(sc[2], sc[3]));
        m = fmaxf(m, __shfl_xor_sync(0xffffffffu, m, 1));
        m = fmaxf(m, __shfl_xor_sync(0xffffffffu, m, 2));
        float ev[4]; float Z = 0.f;
        #pragma unroll
        for (int j = 0; j < 4; j++) { ev[j] = __expf(sc[j] - m); Z += ev[j]; }
        Z += __shfl_xor_sync(0xffffffffu, Z, 1);
        Z += __shfl_xor_sync(0xffffffffu, Z, 2);

        float o[8];
        #pragma unroll
        for (int d = 0; d < 8; d++) o[d] = 0.f;
        #pragma unroll
        for (int x = 0; x < 4; x++) {
            #pragma unroll
            for (int j = 0; j < 4; j++) {
                float ecur = (x == 0) ? ev[j] : __shfl_xor_sync(0xffffffffu, ev[j], x);
                int key = ((p ^ x) << 2) + j;  // 0..15
                const float* vrow = (key < 8) ? &sVd[key][d0] : &sVs[buf][key - 8][d0];
                float4 va = *(const float4*)vrow;
                float4 vb = *(const float4*)(vrow + 4);
                o[0] += ecur * va.x; o[1] += ecur * va.y;
                o[2] += ecur * va.z; o[3] += ecur * va.w;
                o[4] += ecur * vb.x; o[5] += ecur * vb.y;
                o[6] += ecur * vb.z; o[7] += ecur * vb.w;
            }
        }
        float invZ = 1.0f / Z;
        #pragma unroll
        for (int d = 0; d < 8; d++) acc[d] += o[d] * invZ;

        __syncthreads();   // compute done before buf is overwritten next iter
    }

    float* outp = sumO + ((size_t)n * 8 + i) * 128 + d0;
    float4 w0 = make_float4(acc[0], acc[1], acc[2], acc[3]);
    float4 w1 = make_float4(acc[4], acc[5], acc[6], acc[7]);
    *(float4*)outp = w0;
    *(float4*)(outp + 4) = w1;
}

// ---------------- launch ----------------
extern "C" void kernel_launch(void* const* d_in, const int* in_sizes, int n_in,
                              void* d_out, int out_size)
{
    const float* x_a = (const float*)d_in[0];
    const float* x_b = (const float*)d_in[1];
    const int* ei[3] = {(const int*)d_in[2], (const int*)d_in[3], (const int*)d_in[4]};
    const float *Wb[3], *bb[3], *Win[3], *bin[3], *Wo[3], *bo[3];
    for (int r = 0; r < 3; r++) {
        Wb[r]  = (const float*)d_in[5 + 6 * r];
        bb[r]  = (const float*)d_in[6 + 6 * r];
        Win[r] = (const float*)d_in[7 + 6 * r];
        bin[r] = (const float*)d_in[8 + 6 * r];
        Wo[r]  = (const float*)d_in[9 + 6 * r];
        bo[r]  = (const float*)d_in[10 + 6 * r];
    }

    float *projD, *projS, *sumO, *WT, *WTs, *bS, *WoT;
    int *cnt, *offp, *cursor, *srcList;
    cudaGetSymbolAddress((void**)&projD, g_projD);
    cudaGetSymbolAddress((void**)&projS, g_projS);
    cudaGetSymbolAddress((void**)&sumO,  g_sumO);
    cudaGetSymbolAddress((void**)&cnt,   g_cnt);
    cudaGetSymbolAddress((void**)&offp,  g_off);
    cudaGetSymbolAddress((void**)&cursor, g_cursor);
    cudaGetSymbolAddress((void**)&srcList, g_srcList);
    cudaGetSymbolAddress((void**)&WT,    g_WT);
    cudaGetSymbolAddress((void**)&WTs,   g_WTs);
    cudaGetSymbolAddress((void**)&bS,    g_bS);
    cudaGetSymbolAddress((void**)&WoT,   g_WoT);

    float* outA = (float*)d_out;
    float* outB = (float*)d_out + (size_t)NS * 128;

    const float* xs[3]  = {x_a, x_b, x_a};
    const float* xd[3]  = {x_b, x_a, x_a};
    float*       op[3]  = {outB, outA, outA};
    const float  al[3]  = {1.0f, 0.5f, 0.5f};
    const int    ac[3]  = {0, 0, 1};

    for (int r = 0; r < 3; r++) {
        // edge sort by dst
        cudaMemsetAsync(cnt, 0, N_NODES * sizeof(int), 0);
        count_kernel<<<(E_EDGES + 255) / 256, 256>>>(ei[r] + E_EDGES, cnt);
        scan_kernel<<<1, 1024>>>(cnt, offp);
        cudaMemcpyAsync(cursor, offp, N_NODES * sizeof(int), cudaMemcpyDeviceToDevice, 0);
        fill_kernel<<<(E_EDGES + 255) / 256, 256>>>(ei[r], cursor, srcList);

        // weight prep
        transpose_w_kernel<<<(384 * 128 + 255) / 256, 256>>>(Win[r], WT, 384);
        combine_src_kernel<<<128, 128>>>(Win[r], bin[r], Wb[r], bb[r], WTs, bS);
        transpose_w_kernel<<<(128 * 128 + 255) / 256, 256>>>(Wo[r], WoT, 128);

        {   // dst projections: Q | Kd | Vd
            dim3 g(NS / 128, 384 / 128);
            gemm_tf32<<<g, 256>>>(xd[r], WT, bin[r], nullptr, projD, 384, 1.0f, 0);
        }
        {   // src projections: Ks | Vs (Wb folded)
            dim3 g(NS / 128, 256 / 128);
            gemm_tf32<<<g, 256>>>(xs[r], WTs, bS, nullptr, projS, 256, 1.0f, 0);
        }

        // per-dst aggregation (no atomics, no memset, self-scores fused)
        agg_kernel<<<N_NODES, 128>>>(srcList, offp, projD, projS, sumO);

        {   // mean + Wo + gated bias, scaled/accumulated into output
            dim3 g(NS / 128, 128 / 128);
            gemm_tf32<<<g, 256>>>(sumO, WoT, bo[r], cnt, op[r], 128, al[r],
                                  ac[r] | 2 | 4);
        }
    }
}

// round 15
// speedup vs baseline: 3.4829x; 1.1483x over previous
#include <cuda_runtime.h>
#include <cuda_fp16.h>
#include <math.h>
#include <stdint.h>

#define N_NODES 20000
#define S_TOK   8
#define D_DIM   128
#define E_EDGES 100000
#define NS      (N_NODES * S_TOK)   // 160000 rows

// ---------------- static scratch (no allocs allowed) ----------------
__device__ __half g_projD[(size_t)NS * 384];   // per-dst-node Q|Kd|Vd (fp16)
__device__ __half g_projS[(size_t)NS * 256];   // per-src-node Ks|Vs   (fp16)
__device__ float  g_sumO [(size_t)NS * 128];   // attention-output accum (fp32)
__device__ int    g_cnt  [N_NODES];
__device__ int    g_off  [N_NODES + 1];
__device__ int    g_cursor[N_NODES];
__device__ int    g_srcList[E_EDGES];
__device__ float  g_WT   [128 * 384];          // Win transposed [K, 3D]
__device__ float  g_WTs  [128 * 256];          // combined (Wk*Wb | Wv*Wb) transposed
__device__ float  g_bS   [256];                // combined src biases
__device__ float  g_WoT  [128 * 128];          // Wo transposed

// ---------------- helpers ----------------
__device__ __forceinline__ float to_tf32(float x) {
    float r; asm("cvt.rna.tf32.f32 %0, %1;" : "=f"(r) : "f"(x)); return r;
}
__device__ __forceinline__ void mma_tf32(float* c, const uint32_t* a, const uint32_t* b) {
    asm volatile("mma.sync.aligned.m16n8k8.row.col.f32.tf32.tf32.f32 "
        "{%0,%1,%2,%3}, {%4,%5,%6,%7}, {%8,%9}, {%0,%1,%2,%3};"
        : "+f"(c[0]), "+f"(c[1]), "+f"(c[2]), "+f"(c[3])
        : "r"(a[0]), "r"(a[1]), "r"(a[2]), "r"(a[3]), "r"(b[0]), "r"(b[1]));
}
__device__ __forceinline__ uint32_t smem_u32(const void* p) {
    return (uint32_t)__cvta_generic_to_shared(p);
}
#define CP_ASYNC16(smem_addr, gptr) \
    asm volatile("cp.async.ca.shared.global [%0], [%1], 16;" :: "r"(smem_addr), "l"(gptr))
#define CP_COMMIT() asm volatile("cp.async.commit_group;")

// ---------------- counts ----------------
__global__ void count_kernel(const int* __restrict__ dst, int* __restrict__ cnt) {
    int e = blockIdx.x * blockDim.x + threadIdx.x;
    if (e < E_EDGES) atomicAdd(&cnt[dst[e]], 1);
}

// ---------------- exclusive scan of cnt -> off + cursor (single block) ----------------
__global__ __launch_bounds__(1024) void scan_kernel(const int* __restrict__ cnt,
                                                    int* __restrict__ off,
                                                    int* __restrict__ cursor) {
    __shared__ int warp_sums[32];
    __shared__ int s_carry;
    const int tid = threadIdx.x;
    const int lane = tid & 31, wid = tid >> 5;
    if (tid == 0) s_carry = 0;
    __syncthreads();
    const int nchunks = (N_NODES + 1023) / 1024;
    for (int chunk = 0; chunk < nchunks; chunk++) {
        int idx = chunk * 1024 + tid;
        int v = (idx < N_NODES) ? cnt[idx] : 0;
        int x = v;
        #pragma unroll
        for (int o = 1; o < 32; o <<= 1) {
            int y = __shfl_up_sync(0xffffffffu, x, o);
            if (lane >= o) x += y;
        }
        if (lane == 31) warp_sums[wid] = x;
        __syncthreads();
        if (wid == 0) {
            int w = warp_sums[lane];
            #pragma unroll
            for (int o = 1; o < 32; o <<= 1) {
                int y = __shfl_up_sync(0xffffffffu, w, o);
                if (lane >= o) w += y;
            }
            warp_sums[lane] = w;
        }
        __syncthreads();
        int warp_off = (wid > 0) ? warp_sums[wid - 1] : 0;
        int incl = x + warp_off + s_carry;
        if (idx < N_NODES) { off[idx] = incl - v; cursor[idx] = incl - v; }
        if (idx == N_NODES - 1) off[N_NODES] = incl;
        __syncthreads();
        if (tid == 1023) s_carry = incl;
        __syncthreads();
    }
}

// ---------------- scatter edges into dst-sorted src list ----------------
__global__ void fill_kernel(const int* __restrict__ ei, int* __restrict__ cursor,
                            int* __restrict__ srcList) {
    int e = blockIdx.x * blockDim.x + threadIdx.x;
    if (e < E_EDGES) {
        int d = ei[E_EDGES + e];
        int pos = atomicAdd(&cursor[d], 1);
        srcList[pos] = ei[e];
    }
}

// ---------------- weight prep ----------------
__global__ void transpose_w_kernel(const float* __restrict__ W, float* __restrict__ WT, int rows) {
    int idx = blockIdx.x * blockDim.x + threadIdx.x;
    if (idx < rows * 128) {
        int k = idx / rows, o = idx % rows;
        WT[idx] = W[o * 128 + k];
    }
}

__global__ void combine_src_kernel(const float* __restrict__ Win, const float* __restrict__ binp,
                                   const float* __restrict__ Wb,  const float* __restrict__ bb,
                                   float* __restrict__ WTs, float* __restrict__ bS) {
    int o = blockIdx.x;   // 0..127
    int k = threadIdx.x;  // 0..127
    const float* wkrow = Win + (128 + o) * 128;
    const float* wvrow = Win + (256 + o) * 128;
    float sk = 0.f, sv = 0.f;
    for (int j = 0; j < 128; j++) {
        float wb = Wb[j * 128 + k];
        sk += wkrow[j] * wb;
        sv += wvrow[j] * wb;
    }
    WTs[k * 256 + o]       = sk;
    WTs[k * 256 + 128 + o] = sv;
    if (k == 0) {
        float s = 0.f;
        for (int j = 0; j < 128; j++) s += wkrow[j] * bb[j];
        bS[o] = s + binp[128 + o];
    } else if (k == 1) {
        float s = 0.f;
        for (int j = 0; j < 128; j++) s += wvrow[j] * bb[j];
        bS[128 + o] = s + binp[256 + o];
    }
}

// ---------------- tf32 tensor-core GEMM ----------------
// flags: bit0 accumulate(fp32 only); bit1 scale A rows by 1/max(cnt,1); bit2 bias gated by cnt>0;
// bit3 output fp16 (Cout as __half*), else fp32 (Cout as float*).
__global__ __launch_bounds__(256, 2) void gemm_tf32(
    const float* __restrict__ A, const float* __restrict__ B,
    const float* __restrict__ bias, const int* __restrict__ cnt,
    void* __restrict__ Cout, int Nn, float alpha, int flags)
{
    __shared__ float As[2][128][20];
    __shared__ float Bs[2][16][136];
    const int tid = threadIdx.x;
    const int bm = blockIdx.x * 128;
    const int bn = blockIdx.y * 128;
    const int wid = tid >> 5, lane = tid & 31;
    const int wm = (wid & 3) * 32;
    const int wn = (wid >> 2) * 64;
    const int g  = lane >> 2, tg = lane & 3;

    const int ar = tid >> 2;
    const int ac = (tid & 3) * 4;
    float rs0 = 1.f, rs1 = 1.f;
    if (flags & 2) {
        int c0 = cnt[(bm + ar) >> 3];       rs0 = 1.f / (float)(c0 > 1 ? c0 : 1);
        int c1 = cnt[(bm + ar + 64) >> 3];  rs1 = 1.f / (float)(c1 > 1 ? c1 : 1);
    }
    const float* Ap = A + (size_t)(bm + ar) * 128 + ac;
    const int br = tid >> 5;
    const int bc = (tid & 31) * 4;
    const float* Bp = B + (size_t)br * Nn + bn + bc;

    float acc[2][8][4];
    #pragma unroll
    for (int mt = 0; mt < 2; mt++)
        #pragma unroll
        for (int nt = 0; nt < 8; nt++)
            #pragma unroll
            for (int j = 0; j < 4; j++) acc[mt][nt][j] = 0.f;

    float4 ra0 = *(const float4*)(Ap);
    float4 ra1 = *(const float4*)(Ap + (size_t)64 * 128);
    float4 rb0 = *(const float4*)(Bp);
    float4 rb1 = *(const float4*)(Bp + (size_t)8 * Nn);

    #pragma unroll 1
    for (int ch = 0; ch < 8; ch++) {
        const int bsel = ch & 1;
        As[bsel][ar][ac + 0]      = to_tf32(ra0.x * rs0);
        As[bsel][ar][ac + 1]      = to_tf32(ra0.y * rs0);
        As[bsel][ar][ac + 2]      = to_tf32(ra0.z * rs0);
        As[bsel][ar][ac + 3]      = to_tf32(ra0.w * rs0);
        As[bsel][ar + 64][ac + 0] = to_tf32(ra1.x * rs1);
        As[bsel][ar + 64][ac + 1] = to_tf32(ra1.y * rs1);
        As[bsel][ar + 64][ac + 2] = to_tf32(ra1.z * rs1);
        As[bsel][ar + 64][ac + 3] = to_tf32(ra1.w * rs1);
        Bs[bsel][br][bc + 0]      = to_tf32(rb0.x);
        Bs[bsel][br][bc + 1]      = to_tf32(rb0.y);
        Bs[bsel][br][bc + 2]      = to_tf32(rb0.z);
        Bs[bsel][br][bc + 3]      = to_tf32(rb0.w);
        Bs[bsel][br + 8][bc + 0]  = to_tf32(rb1.x);
        Bs[bsel][br + 8][bc + 1]  = to_tf32(rb1.y);
        Bs[bsel][br + 8][bc + 2]  = to_tf32(rb1.z);
        Bs[bsel][br + 8][bc + 3]  = to_tf32(rb1.w);
        __syncthreads();

        if (ch < 7) {
            const int k0 = (ch + 1) * 16;
            ra0 = *(const float4*)(Ap + k0);
            ra1 = *(const float4*)(Ap + (size_t)64 * 128 + k0);
            rb0 = *(const float4*)(Bp + (size_t)k0 * Nn);
            rb1 = *(const float4*)(Bp + (size_t)(k0 + 8) * Nn);
        }

        #pragma unroll
        for (int kk = 0; kk < 2; kk++) {
            uint32_t af[2][4], bf[8][2];
            #pragma unroll
            for (int mt = 0; mt < 2; mt++) {
                const float* a0p = &As[bsel][wm + mt * 16 + g][kk * 8 + tg];
                const float* a1p = &As[bsel][wm + mt * 16 + g + 8][kk * 8 + tg];
                af[mt][0] = __float_as_uint(a0p[0]);
                af[mt][1] = __float_as_uint(a1p[0]);
                af[mt][2] = __float_as_uint(a0p[4]);
                af[mt][3] = __float_as_uint(a1p[4]);
            }
            #pragma unroll
            for (int nt = 0; nt < 8; nt++) {
                bf[nt][0] = __float_as_uint(Bs[bsel][kk * 8 + tg][wn + nt * 8 + g]);
                bf[nt][1] = __float_as_uint(Bs[bsel][kk * 8 + 4 + tg][wn + nt * 8 + g]);
            }
            #pragma unroll
            for (int mt = 0; mt < 2; mt++)
                #pragma unroll
                for (int nt = 0; nt < 8; nt++)
                    mma_tf32(acc[mt][nt], af[mt], bf[nt]);
        }
    }

    #pragma unroll
    for (int mt = 0; mt < 2; mt++) {
        #pragma unroll
        for (int ri = 0; ri < 2; ri++) {
            const int row = bm + wm + mt * 16 + g + ri * 8;
            float ind = 1.0f;
            if (flags & 4) ind = (cnt[row >> 3] > 0) ? 1.0f : 0.0f;
            const int colb = bn + wn + tg * 2;
            #pragma unroll
            for (int nt = 0; nt < 8; nt++) {
                float b0 = 0.f, b1 = 0.f;
                if (bias) {
                    b0 = bias[colb + nt * 8 + 0];
                    b1 = bias[colb + nt * 8 + 1];
                }
                float v0 = alpha * (acc[mt][nt][ri * 2 + 0] + b0 * ind);
                float v1 = alpha * (acc[mt][nt][ri * 2 + 1] + b1 * ind);
                if (flags & 8) {
                    __half2* hp = (__half2*)((__half*)Cout + (size_t)row * Nn + colb + nt * 8);
                    *hp = __floats2half2_rn(v0, v1);
                } else {
                    float* cp = (float*)Cout + (size_t)row * Nn + colb + nt * 8;
                    if (flags & 1) { cp[0] += v0; cp[1] += v1; }
                    else           { cp[0]  = v0; cp[1]  = v1; }
                }
            }
        }
    }
}

// ---------------- per-dst-node aggregation (fp16 proj inputs) ----------------
// One block per dst node, 4 warps = 4 heads. Tiles stored as half2 in smem.
__global__ __launch_bounds__(128) void agg_kernel(
    const int* __restrict__ srcList, const int* __restrict__ off,
    const __half* __restrict__ projD, const __half* __restrict__ projS,
    float* __restrict__ sumO)
{
    __shared__ __half2 sQ [8][68];     // 64 half2 per row + pad
    __shared__ __half2 sVd[8][68];
    __shared__ __half2 sKs[2][8][68];
    __shared__ __half2 sVs[2][8][68];
    __shared__ float sS[256];
    const int n   = blockIdx.x;
    const int tid = threadIdx.x;
    const int base = off[n];
    const int deg  = off[n + 1] - base;

    // load Q, Vd; Kd temporarily into sKs[1]. Each tile = 8 rows x 64 half2 = 128 x 16B chunks.
    {
        const __half2* dbase = (const __half2*)(projD + (size_t)n * 3072);
        const int r = tid >> 4, cc = (tid & 15) * 4;         // half2 units
        const __half2* rowp = dbase + r * 192 + cc;
        *(uint4*)&sQ [r][cc]    = *(const uint4*)(rowp);        // Q  (+0)
        *(uint4*)&sKs[1][r][cc] = *(const uint4*)(rowp + 64);   // Kd (+64 half2)
        *(uint4*)&sVd[r][cc]    = *(const uint4*)(rowp + 128);  // Vd (+128 half2)
    }
    __syncthreads();

    // prefetch edge 0 into buffer 0
    if (deg > 0) {
        const __half2* sbase = (const __half2*)(projS + (size_t)srcList[base] * 2048);
        const int r = tid >> 4, cc = (tid & 15) * 4;
        CP_ASYNC16(smem_u32(&sKs[0][r][cc]), sbase + r * 128 + cc);
        CP_ASYNC16(smem_u32(&sVs[0][r][cc]), sbase + r * 128 + 64 + cc);
    }
    CP_COMMIT();

    const float scale = 0.17677669529663687f;  // 1/sqrt(32)
    // self scores S[h][i][j] (Kd in sKs[1])
    #pragma unroll
    for (int t = tid; t < 256; t += 128) {
        int hh = t >> 6, ii = (t >> 3) & 7, jj = t & 7;
        const __half2* qp = &sQ[ii][hh * 16];
        const __half2* kp = &sKs[1][jj][hh * 16];
        float s = 0.f;
        #pragma unroll
        for (int d = 0; d < 16; d++) {
            float2 qf = __half22float2(qp[d]);
            float2 kf = __half22float2(kp[d]);
            s += qf.x * kf.x + qf.y * kf.y;
        }
        sS[t] = s * scale;
    }

    const int h    = tid >> 5;
    const int lane = tid & 31;
    const int i    = lane >> 2;
    const int p    = lane & 3;
    const int h2c0 = h * 16;           // head base in half2 units
    const int d0h2 = h2c0 + (p << 2);  // this lane's 8-float slice in half2 units

    float q[32];
    #pragma unroll
    for (int d = 0; d < 16; d++) {
        float2 qf = __half22float2(sQ[i][h2c0 + d]);
        q[2 * d] = qf.x; q[2 * d + 1] = qf.y;
    }

    __syncthreads();   // sS visible; Kd-temp (sKs[1]) free for reuse

    float acc[8];
    #pragma unroll
    for (int d = 0; d < 8; d++) acc[d] = 0.f;

    #pragma unroll 1
    for (int t = 0; t < deg; t++) {
        const int buf = t & 1;
        if (t + 1 < deg) {
            const __half2* sbase = (const __half2*)(projS + (size_t)srcList[base + t + 1] * 2048);
            const int r = tid >> 4, cc = (tid & 15) * 4;
            CP_ASYNC16(smem_u32(&sKs[buf ^ 1][r][cc]), sbase + r * 128 + cc);
            CP_ASYNC16(smem_u32(&sVs[buf ^ 1][r][cc]), sbase + r * 128 + 64 + cc);
        }
        CP_COMMIT();
        asm volatile("cp.async.wait_group 1;");
        __syncthreads();

        // cross scores for source keys 2p, 2p+1
        float s0 = 0.f, s1 = 0.f;
        {
            const __half2* k0p = &sKs[buf][2 * p][h2c0];
            const __half2* k1p = &sKs[buf][2 * p + 1][h2c0];
            #pragma unroll
            for (int d = 0; d < 16; d++) {
                float2 k0f = __half22float2(k0p[d]);
                float2 k1f = __half22float2(k1p[d]);
                s0 += q[2 * d] * k0f.x + q[2 * d + 1] * k0f.y;
                s1 += q[2 * d] * k1f.x + q[2 * d + 1] * k1f.y;
            }
            s0 *= scale; s1 *= scale;
        }

        float sc[4];
        #pragma unroll
        for (int j = 0; j < 4; j++) {
            int srcLane = (i << 2) + (((p - 2) & 1) << 1) + (j >> 1);
            float c0v = __shfl_sync(0xffffffffu, s0, srcLane);
            float c1v = __shfl_sync(0xffffffffu, s1, srcLane);
            float cross = (j & 1) ? c1v : c0v;
            sc[j] = (p < 2) ? sS[h * 64 + i * 8 + p * 4 + j] : cross;
        }

        float m = fmaxf(fmaxf(sc[0], sc[1]), fmaxf(sc[2], sc[3]));
        m = fmaxf(m, __shfl_xor_sync(0xffffffffu, m, 1));
        m = fmaxf(m, __shfl_xor_sync(0xffffffffu, m, 2));
        float ev[4]; float Z = 0.f;
        #pragma unroll
        for (int j = 0; j < 4; j++) { ev[j] = __expf(sc[j] - m); Z += ev[j]; }
        Z += __shfl_xor_sync(0xffffffffu, Z, 1);
        Z += __shfl_xor_sync(0xffffffffu, Z, 2);

        float o[8];
        #pragma unroll
        for (int d = 0; d < 8; d++) o[d] = 0.f;
        #pragma unroll
        for (int x = 0; x < 4; x++) {
            #pragma unroll
            for (int j = 0; j < 4; j++) {
                float ecur = (x == 0) ? ev[j] : __shfl_xor_sync(0xffffffffu, ev[j], x);
                int key = ((p ^ x) << 2) + j;  // 0..15
                const __half2* vrow = (key < 8) ? &sVd[key][d0h2] : &sVs[buf][key - 8][d0h2];
                #pragma unroll
                for (int d = 0; d < 4; d++) {
                    float2 vf = __half22float2(vrow[d]);
                    o[2 * d]     += ecur * vf.x;
                    o[2 * d + 1] += ecur * vf.y;
                }
            }
        }
        float invZ = 1.0f / Z;
        #pragma unroll
        for (int d = 0; d < 8; d++) acc[d] += o[d] * invZ;

        __syncthreads();
    }

    float* outp = sumO + ((size_t)n * 8 + i) * 128 + h * 32 + p * 8;
    *(float4*)outp       = make_float4(acc[0], acc[1], acc[2], acc[3]);
    *(float4*)(outp + 4) = make_float4(acc[4], acc[5], acc[6], acc[7]);
}

// ---------------- launch ----------------
extern "C" void kernel_launch(void* const* d_in, const int* in_sizes, int n_in,
                              void* d_out, int out_size)
{
    const float* x_a = (const float*)d_in[0];
    const float* x_b = (const float*)d_in[1];
    const int* ei[3] = {(const int*)d_in[2], (const int*)d_in[3], (const int*)d_in[4]};
    const float *Wb[3], *bb[3], *Win[3], *bin[3], *Wo[3], *bo[3];
    for (int r = 0; r < 3; r++) {
        Wb[r]  = (const float*)d_in[5 + 6 * r];
        bb[r]  = (const float*)d_in[6 + 6 * r];
        Win[r] = (const float*)d_in[7 + 6 * r];
        bin[r] = (const float*)d_in[8 + 6 * r];
        Wo[r]  = (const float*)d_in[9 + 6 * r];
        bo[r]  = (const float*)d_in[10 + 6 * r];
    }

    __half *projD, *projS;
    float *sumO, *WT, *WTs, *bS, *WoT;
    int *cnt, *offp, *cursor, *srcList;
    cudaGetSymbolAddress((void**)&projD, g_projD);
    cudaGetSymbolAddress((void**)&projS, g_projS);
    cudaGetSymbolAddress((void**)&sumO,  g_sumO);
    cudaGetSymbolAddress((void**)&cnt,   g_cnt);
    cudaGetSymbolAddress((void**)&offp,  g_off);
    cudaGetSymbolAddress((void**)&cursor, g_cursor);
    cudaGetSymbolAddress((void**)&srcList, g_srcList);
    cudaGetSymbolAddress((void**)&WT,    g_WT);
    cudaGetSymbolAddress((void**)&WTs,   g_WTs);
    cudaGetSymbolAddress((void**)&bS,    g_bS);
    cudaGetSymbolAddress((void**)&WoT,   g_WoT);

    float* outA = (float*)d_out;
    float* outB = (float*)d_out + (size_t)NS * 128;

    const float* xs[3]  = {x_a, x_b, x_a};
    const float* xd[3]  = {x_b, x_a, x_a};
    float*       op[3]  = {outB, outA, outA};
    const float  al[3]  = {1.0f, 0.5f, 0.5f};
    const int    ac[3]  = {0, 0, 1};

    for (int r = 0; r < 3; r++) {
        // edge sort by dst
        cudaMemsetAsync(cnt, 0, N_NODES * sizeof(int), 0);
        count_kernel<<<(E_EDGES + 255) / 256, 256>>>(ei[r] + E_EDGES, cnt);
        scan_kernel<<<1, 1024>>>(cnt, offp, cursor);
        fill_kernel<<<(E_EDGES + 255) / 256, 256>>>(ei[r], cursor, srcList);

        // weight prep
        transpose_w_kernel<<<(384 * 128 + 255) / 256, 256>>>(Win[r], WT, 384);
        combine_src_kernel<<<128, 128>>>(Win[r], bin[r], Wb[r], bb[r], WTs, bS);
        transpose_w_kernel<<<(128 * 128 + 255) / 256, 256>>>(Wo[r], WoT, 128);

        {   // dst projections: Q | Kd | Vd  -> fp16
            dim3 g(NS / 128, 384 / 128);
            gemm_tf32<<<g, 256>>>(xd[r], WT, bin[r], nullptr, projD, 384, 1.0f, 8);
        }
        {   // src projections: Ks | Vs (Wb folded) -> fp16
            dim3 g(NS / 128, 256 / 128);
            gemm_tf32<<<g, 256>>>(xs[r], WTs, bS, nullptr, projS, 256, 1.0f, 8);
        }

        // per-dst aggregation (no atomics, fused self-scores, fp16 gather)
        agg_kernel<<<N_NODES, 128>>>(srcList, offp, projD, projS, sumO);

        {   // mean + Wo + gated bias, scaled/accumulated into fp32 output
            dim3 g(NS / 128, 128 / 128);
            gemm_tf32<<<g, 256>>>(sumO, WoT, bo[r], cnt, op[r], 128, al[r],
                                  ac[r] | 2 | 4);
        }
    }
}